// round 6
// baseline (speedup 1.0000x reference)
#include <cuda_runtime.h>
#include <cfloat>

#define NPTS 4096
#define MQ   1024
#define CCH  64
#define GRID 20
#define NCELL (GRID * GRID)
#define CAP  64          // points per cell; lambda=10.24, overflow prob ~1e-30

__device__ float2 g_xy[NCELL * CAP];   // cell-sorted coords
__device__ int    g_id [NCELL * CAP];  // cell-sorted point indices
__device__ int    g_cnt[NCELL];        // per-cell counts

__device__ __forceinline__ int cellof(float v) {
    int c = (int)(v * 20.0f);
    return min(GRID - 1, max(0, c));
}

// ---- Pass 1: bin all points into 20x20 grid (single block) ----
__global__ __launch_bounds__(1024, 1)
void bin_kernel(const float* __restrict__ coords) {
    __shared__ int s_cnt[NCELL];
    const int tid = threadIdx.x;

    for (int i = tid; i < NCELL; i += 1024) s_cnt[i] = 0;
    __syncthreads();

    const float2* __restrict__ c2 = (const float2*)coords;
    #pragma unroll
    for (int i = tid; i < NPTS; i += 1024) {
        float2 c = c2[i];
        int cell = cellof(c.y) * GRID + cellof(c.x);
        int pos = atomicAdd(&s_cnt[cell], 1);
        if (pos < CAP) {
            g_xy[cell * CAP + pos] = c;
            g_id[cell * CAP + pos] = i;
        }
    }
    __syncthreads();

    for (int i = tid; i < NCELL; i += 1024) g_cnt[i] = min(s_cnt[i], CAP);
}

// ---- Pass 2: per-query gather-max over candidate cells ----
__global__ __launch_bounds__(256, 4)
void maxpool_query_kernel(const float* __restrict__ values,
                          const float* __restrict__ qcoords,
                          float* __restrict__ out) {
    __shared__ int   s_idx[1024];
    __shared__ int   s_count;
    __shared__ float s_red[4][CCH];

    const int q    = blockIdx.x;
    const int tid  = threadIdx.x;
    const int lane = tid & 31;
    const int wid  = tid >> 5;

    const float qx = qcoords[2 * q];
    const float qy = qcoords[2 * q + 1];

    if (tid == 0) s_count = 0;
    __syncthreads();

    // Candidate cell range (margin absorbs float rounding at cell boundaries;
    // the exact mask test below decides actual membership).
    const int xlo = cellof(qx - 0.0500010f);
    const int xhi = cellof(qx + 0.0500010f);
    const int ylo = cellof(qy - 0.0500010f);
    const int yhi = cellof(qy + 0.0500010f);
    const int nx = xhi - xlo + 1;
    const int ncells = nx * (yhi - ylo + 1);

    // Warp per cell: test bucket coords, push matching indices.
    for (int ci = wid; ci < ncells; ci += 8) {
        const int cell = (ylo + ci / nx) * GRID + (xlo + ci % nx);
        const int cnt  = g_cnt[cell];
        for (int j = lane; j < cnt; j += 32) {
            float2 c = g_xy[cell * CAP + j];
            if (fabsf(qx - c.x) < 0.05f && fabsf(qy - c.y) < 0.05f) {
                int p = atomicAdd(&s_count, 1);
                s_idx[p] = g_id[cell * CAP + j];
            }
        }
    }
    __syncthreads();

    const int cnt   = s_count;
    const int ch    = tid & (CCH - 1);   // channel 0..63
    const int slice = tid >> 6;          // candidate slice 0..3

    // Gather-max: 64 consecutive channels per row -> coalesced 256B reads.
    float m = -FLT_MAX;
    for (int j = slice; j < cnt; j += 4) {
        m = fmaxf(m, values[s_idx[j] * CCH + ch]);
    }
    s_red[slice][ch] = m;
    __syncthreads();

    if (tid < CCH) {
        float r = fmaxf(fmaxf(s_red[0][tid], s_red[1][tid]),
                        fmaxf(s_red[2][tid], s_red[3][tid]));
        out[q * CCH + tid] = r;
    }
}

extern "C" void kernel_launch(void* const* d_in, const int* in_sizes, int n_in,
                              void* d_out, int out_size) {
    const float* values  = (const float*)d_in[0];   // [N, C] f32
    const float* coords  = (const float*)d_in[1];   // [N, 2] f32
    const float* qcoords = (const float*)d_in[2];   // [M, 2] f32
    float* out = (float*)d_out;                     // [M, C] f32

    bin_kernel<<<1, 1024>>>(coords);
    maxpool_query_kernel<<<MQ, 256>>>(values, qcoords, out);
}